// round 1
// baseline (speedup 1.0000x reference)
#include <cuda_runtime.h>
#include <math.h>

#define BB 2
#define PP 19248
#define NN 100
#define KK 20
#define HG 32
#define HP 138
#define WP 138
#define HH 550
#define WW 550
#define DM 32
#define NPAIR 4950  // NN*(NN-1)/2

// ---------------- scratch (device globals; no allocation allowed) ----------------
__device__ int    g_sIdx[BB][NN];
__device__ float  g_sConf[BB][NN];
__device__ float  g_sLoc[BB][NN][4];
__device__ float  g_gauss[BB][NN][HG * HG];
__device__ float  g_gsum[BB][NN];
__device__ float  g_iou[BB][NN][NN];   // only upper triangle (i<j) is written/read
__device__ int    g_keep[BB][KK];
__device__ float  g_kConf[BB][KK];
__device__ float  g_kLoc[BB][KK][4];
__device__ float  g_kMask[BB][KK][DM];
__device__ float  g_fconf[BB][HP * WP];
__device__ double g_accum[2];          // [0]=var sum, [1]=ae sum

// ---------------- helpers ----------------
__device__ __forceinline__ float blockReduceSum(float v, float* sm) {
    int lane = threadIdx.x & 31, warp = threadIdx.x >> 5;
#pragma unroll
    for (int o = 16; o; o >>= 1) v += __shfl_down_sync(0xffffffffu, v, o);
    if (lane == 0) sm[warp] = v;
    __syncthreads();
    int nw = (blockDim.x + 31) >> 5;
    v = (threadIdx.x < nw) ? sm[threadIdx.x] : 0.f;
    if (warp == 0) {
#pragma unroll
        for (int o = 16; o; o >>= 1) v += __shfl_down_sync(0xffffffffu, v, o);
    }
    return v;  // valid in thread 0
}

// ---------------- kernel 1: softmax + exact top-100 (value desc, index asc) ----------------
// One block per batch, 1024 threads. Values live in dynamic smem; each thread
// keeps its stripe-max candidate in a register; each iteration does a block max
// reduce, records the winner, clears it, and only the owner thread rescans.
__global__ void k_topk(const float* __restrict__ conf, const float* __restrict__ loc) {
    extern __shared__ float vals[];                 // PP floats
    __shared__ unsigned long long wred[32];
    __shared__ unsigned long long winner;
    int b = blockIdx.x, t = threadIdx.x;

    const float* cb = conf + (size_t)b * PP * 2;
    for (int i = t; i < PP; i += 1024) {
        float c0 = cb[2 * i], c1 = cb[2 * i + 1];
        float m = fmaxf(c0, c1);
        float e0 = expf(c0 - m), e1 = expf(c1 - m);
        vals[i] = e1 / (e0 + e1);                   // softmax(...)[:,1], strictly in (0,1)
    }
    if (b == 0 && t < 2) g_accum[t] = 0.0;
    __syncthreads();

    // initial per-thread candidate (strided stripe: i = t + k*1024)
    unsigned long long cand = 0ULL;
#pragma unroll
    for (int k = 0; k < 19; k++) {
        int i = t + k * 1024;
        if (i < PP) {
            float v = vals[i];
            if (v > 0.f) {
                unsigned long long key =
                    ((unsigned long long)__float_as_uint(v) << 32) | (unsigned)(~i);
                if (key > cand) cand = key;
            }
        }
    }
    int lane = t & 31, warp = t >> 5;

    for (int r = 0; r < NN; r++) {
        unsigned long long m = cand;
#pragma unroll
        for (int o = 16; o; o >>= 1) {
            unsigned long long x = __shfl_down_sync(0xffffffffu, m, o);
            if (x > m) m = x;
        }
        if (lane == 0) wred[warp] = m;
        __syncthreads();
        if (t < 32) {
            unsigned long long x = wred[t];
#pragma unroll
            for (int o = 16; o; o >>= 1) {
                unsigned long long y = __shfl_down_sync(0xffffffffu, x, o);
                if (y > x) x = y;
            }
            if (t == 0) winner = x;
        }
        __syncthreads();
        unsigned long long w = winner;
        int idx = (int)(~((unsigned)w));            // low 32 bits were ~i
        if (t == (idx & 1023)) {                    // owner thread of that stripe
            g_sIdx[b][r] = idx;
            g_sConf[b][r] = __uint_as_float((unsigned)(w >> 32));
            vals[idx] = -1.f;
            cand = 0ULL;
#pragma unroll
            for (int k = 0; k < 19; k++) {
                int i = t + k * 1024;
                if (i < PP) {
                    float v = vals[i];
                    if (v > 0.f) {
                        unsigned long long key =
                            ((unsigned long long)__float_as_uint(v) << 32) | (unsigned)(~i);
                        if (key > cand) cand = key;
                    }
                }
            }
        }
        __syncthreads();
    }

    // gather sorted loc
    const float* lb = loc + (size_t)b * PP * 4;
    if (t < NN * 4) {
        int r = t >> 2, c = t & 3;
        g_sLoc[b][r][c] = lb[(size_t)g_sIdx[b][r] * 4 + c];
    }
}

// ---------------- kernel 2: 32x32 gaussians for top-100 + row sums ----------------
__global__ void k_gauss() {
    __shared__ float sm[32];
    int n = blockIdx.x, b = blockIdx.y, t = threadIdx.x;  // 256 threads
    float cx = g_sLoc[b][n][0], cy = g_sLoc[b][n][1];
    float wv = g_sLoc[b][n][2] + 1e-4f, hv = g_sLoc[b][n][3] + 1e-4f;
    float local = 0.f;
    for (int p = t; p < HG * HG; p += 256) {
        int y = p >> 5, x = p & 31;
        float dx = ((x + 0.5f) / (float)HG - cx) / wv;
        float dy = ((y + 0.5f) / (float)HG - cy) / hv;
        float g = expf(-0.5f * (dx * dx + dy * dy));
        g_gauss[b][n][p] = g;
        local += g;
    }
    float s = blockReduceSum(local, sm);
    if (t == 0) g_gsum[b][n] = s;
}

// ---------------- kernel 3: pairwise gaussian IoU (upper triangle) ----------------
__global__ void k_iou() {
    __shared__ float sm[32];
    int pid = blockIdx.x, b = blockIdx.y, t = threadIdx.x;  // 128 threads
    // map pid -> (i, j), i<j. base(i) = i*(199-i)/2
    int i = (int)((199.0 - sqrt(199.0 * 199.0 - 8.0 * (double)pid)) * 0.5);
    if (i < 0) i = 0;
    if (i > NN - 2) i = NN - 2;
    while (i < NN - 2 && (i + 1) * (198 - i) / 2 <= pid) ++i;
    while (i > 0 && i * (199 - i) / 2 > pid) --i;
    int j = i + 1 + (pid - i * (199 - i) / 2);

    const float* gi = g_gauss[b][i];
    const float* gj = g_gauss[b][j];
    float local = 0.f;
    for (int p = t; p < HG * HG; p += 128) local += fminf(gi[p], gj[p]);
    float inter = blockReduceSum(local, sm);
    if (t == 0) {
        float u = g_gsum[b][i] + g_gsum[b][j] - inter;
        g_iou[b][i][j] = inter / u;
    }
}

// ---------------- kernel 4: iou_max, keep top-20 (min iou_max, index asc), gathers, AE loss ----------------
__global__ void k_keep(const float* __restrict__ mask) {
    __shared__ float ioumax[NN];
    __shared__ int keep_s[KK];
    __shared__ float aepart[KK];
    int b = blockIdx.x, t = threadIdx.x;  // 128 threads

    if (t < NN) {
        float m = 0.f;  // triu(iou,1): column j=t over rows i<t; zeros elsewhere -> max>=0
        for (int i = 0; i < t; i++) m = fmaxf(m, g_iou[b][i][t]);
        ioumax[t] = m;
    }
    __syncthreads();

    // warp 0: 20 iterations of min over (value bits, index) keys
    if (t < 32) {
        for (int r = 0; r < KK; r++) {
            unsigned long long best = ~0ULL;
            for (int j = t; j < NN; j += 32) {
                unsigned long long key =
                    ((unsigned long long)__float_as_uint(ioumax[j]) << 32) | (unsigned)j;
                if (key < best) best = key;
            }
#pragma unroll
            for (int o = 16; o; o >>= 1) {
                unsigned long long x = __shfl_down_sync(0xffffffffu, best, o);
                if (x < best) best = x;
            }
            best = __shfl_sync(0xffffffffu, best, 0);
            int j = (int)(unsigned)best;
            if (t == 0) {
                keep_s[r] = j;
                ioumax[j] = 3.4e38f;  // exclude from further picks
            }
            __syncwarp();
        }
    }
    __syncthreads();

    // gathers
    if (t < KK) {
        int j = keep_s[t];
        g_keep[b][t] = j;
        g_kConf[b][t] = g_sConf[b][j];
    }
    if (t < KK * 4) {
        int k = t >> 2, c = t & 3;
        g_kLoc[b][k][c] = g_sLoc[b][keep_s[k]][c];
    }
    for (int q = t; q < KK * DM; q += 128) {
        int k = q / DM, d = q % DM;
        int oi = g_sIdx[b][keep_s[k]];
        g_kMask[b][k][d] = mask[((size_t)b * PP + oi) * DM + d];
    }
    __syncthreads();

    // AE: sum_k mean(kLoc^2) * conf[i] * sum_{j>i} iou[i,j]*conf[j], i = keep[k]
    if (t < KK) {
        int i = keep_s[t];
        float rs = 0.f;
        for (int j = i + 1; j < NN; j++) rs += g_iou[b][i][j] * g_sConf[b][j];
        float al = 0.f;
#pragma unroll
        for (int c = 0; c < 4; c++) {
            float v = g_kLoc[b][t][c];
            al += v * v;
        }
        al *= 0.25f;
        aepart[t] = al * g_sConf[b][i] * rs;
    }
    __syncthreads();
    if (t == 0) {
        double s = 0.0;
        for (int k = 0; k < KK; k++) s += (double)aepart[k];
        atomicAdd(&g_accum[1], s);
    }
}

// ---------------- kernel 5: assembled*gauss*conf -> final_conf on 138x138 ----------------
__global__ void k_fconf(const float* __restrict__ proto) {
    __shared__ float sm_mask[KK][DM];
    __shared__ float sm_loc[KK][4];
    __shared__ float sm_conf[KK];
    int b = blockIdx.y, t = threadIdx.x;  // 128 threads

    for (int q = t; q < KK * DM; q += 128) sm_mask[q / DM][q % DM] = g_kMask[b][q / DM][q % DM];
    if (t < KK * 4) sm_loc[t >> 2][t & 3] = g_kLoc[b][t >> 2][t & 3];
    if (t < KK) sm_conf[t] = g_kConf[b][t];
    __syncthreads();

    int pix = blockIdx.x * 128 + t;
    if (pix >= HP * WP) return;
    int y = pix / WP, x = pix - y * WP;

    const float4* pp = (const float4*)(proto + ((size_t)b * HP * WP + pix) * DM);
    float pr[DM];
#pragma unroll
    for (int q = 0; q < DM / 4; q++) {
        float4 v = pp[q];
        pr[4 * q] = v.x; pr[4 * q + 1] = v.y; pr[4 * q + 2] = v.z; pr[4 * q + 3] = v.w;
    }
    float px_ = (x + 0.5f) / (float)WP, py_ = (y + 0.5f) / (float)HP;
    float s1 = 0.f, s2 = 0.f;
#pragma unroll
    for (int k = 0; k < KK; k++) {
        const float4* mk = (const float4*)sm_mask[k];
        float dot = 0.f;
#pragma unroll
        for (int q = 0; q < DM / 4; q++) {
            float4 mv = mk[q];
            dot = fmaf(pr[4 * q], mv.x, dot);
            dot = fmaf(pr[4 * q + 1], mv.y, dot);
            dot = fmaf(pr[4 * q + 2], mv.z, dot);
            dot = fmaf(pr[4 * q + 3], mv.w, dot);
        }
        float a = 1.f / (1.f + expf(-dot));  // sigmoid
        float dx = (px_ - sm_loc[k][0]) / (sm_loc[k][2] + 1e-4f);
        float dy = (py_ - sm_loc[k][1]) / (sm_loc[k][3] + 1e-4f);
        float ug = expf(-0.5f * (dx * dx + dy * dy));
        float mc = a * ug * sm_conf[k];
        s1 += mc;
        s2 = fmaf(mc, mc, s2);
    }
    float fc = 1.f - s2 / (s1 + 1e-6f);
    if (isnan(fc)) fc = 0.f;
    g_fconf[b][pix] = fc;
}

// ---------------- kernel 6: fused bilinear resize (half-pixel, clamp) + weighted variance ----------------
__global__ void k_var(const float* __restrict__ orig) {
    __shared__ float sm[32];
    int pix = blockIdx.x * 256 + threadIdx.x;
    float local = 0.f;
    if (pix < HH * WW) {
        int h = pix / WW, w = pix - h * WW;
        const float scale = (float)HP / (float)HH;  // 138/550, square
        float sx = (w + 0.5f) * scale - 0.5f;
        float sy = (h + 0.5f) * scale - 0.5f;
        float fx0 = floorf(sx), fy0 = floorf(sy);
        float ax = sx - fx0, ay = sy - fy0;
        int x0 = min(max((int)fx0, 0), WP - 1);
        int x1 = min(max((int)fx0 + 1, 0), WP - 1);
        int y0 = min(max((int)fy0, 0), HP - 1);
        int y1 = min(max((int)fy0 + 1, 0), HP - 1);
        float w00 = (1.f - ax) * (1.f - ay), w01 = ax * (1.f - ay);
        float w10 = (1.f - ax) * ay, w11 = ax * ay;

        float r0 = g_fconf[0][y0 * WP + x0] * w00 + g_fconf[0][y0 * WP + x1] * w01 +
                   g_fconf[0][y1 * WP + x0] * w10 + g_fconf[0][y1 * WP + x1] * w11;
        float r1 = g_fconf[1][y0 * WP + x0] * w00 + g_fconf[1][y0 * WP + x1] * w01 +
                   g_fconf[1][y1 * WP + x0] * w10 + g_fconf[1][y1 * WP + x1] * w11;
        float total = r0 + r1;
#pragma unroll
        for (int c = 0; c < 3; c++) {
            float o0 = orig[((size_t)(0 * 3 + c) * HH + h) * WW + w];
            float o1 = orig[((size_t)(1 * 3 + c) * HH + h) * WW + w];
            float wm = (o0 * r0 + o1 * r1) / total;
            float d0 = o0 - wm, d1 = o1 - wm;
            local += (d0 * d0 * r0 + d1 * d1 * r1) / (total + 1e-6f);
        }
    }
    float s = blockReduceSum(local, sm);
    if (threadIdx.x == 0) atomicAdd(&g_accum[0], (double)s);
}

// ---------------- kernel 7: finalize ----------------
__global__ void k_fin(float* out) {
    out[0] = (float)(g_accum[0] / (double)HP * (double)BB);
    out[1] = (float)(g_accum[1] / (double)(BB * NN * NN));
}

// ---------------- launch ----------------
extern "C" void kernel_launch(void* const* d_in, const int* in_sizes, int n_in,
                              void* d_out, int out_size) {
    const float *orig = nullptr, *loc = nullptr, *conf = nullptr, *mask = nullptr, *proto = nullptr;
    for (int i = 0; i < n_in; i++) {
        switch (in_sizes[i]) {
            case BB * 3 * HH * WW:   orig  = (const float*)d_in[i]; break;  // 1815000
            case BB * PP * 4:        loc   = (const float*)d_in[i]; break;  // 153984
            case BB * PP * 2:        conf  = (const float*)d_in[i]; break;  // 76992
            case BB * PP * DM:       mask  = (const float*)d_in[i]; break;  // 1231872
            case BB * HP * WP * DM:  proto = (const float*)d_in[i]; break;  // 1218816
            default: break;
        }
    }
    if (!orig || !loc || !conf || !mask || !proto) return;

    cudaFuncSetAttribute(k_topk, cudaFuncAttributeMaxDynamicSharedMemorySize, PP * sizeof(float));

    k_topk<<<BB, 1024, PP * sizeof(float)>>>(conf, loc);
    k_gauss<<<dim3(NN, BB), 256>>>();
    k_iou<<<dim3(NPAIR, BB), 128>>>();
    k_keep<<<BB, 128>>>(mask);
    k_fconf<<<dim3((HP * WP + 127) / 128, BB), 128>>>(proto);
    k_var<<<(HH * WW + 255) / 256, 256>>>(orig);
    k_fin<<<1, 1>>>((float*)d_out);
}

// round 6
// speedup vs baseline: 1.3633x; 1.3633x over previous
#include <cuda_runtime.h>
#include <math.h>

#define BB 2
#define PP 19248
#define NN 100
#define KK 20
#define HG 32
#define HP 138
#define WP 138
#define HH 550
#define WW 550
#define DM 32
#define TI 8
#define NT 13             // ceil(NN/TI)
#define NTP (NT*(NT+1)/2) // 91 tile pairs (ti<=tj)
#define VAR_BLOCKS ((HH * WW + 255) / 256)

// ---------------- scratch (device globals; no allocation allowed) ----------------
__device__ int      g_sIdx[BB][NN];
__device__ float    g_sConf[BB][NN];
__device__ float    g_sLoc[BB][NN][4];
__device__ float    g_gauss[BB][NN][HG * HG];
__device__ float    g_gsum[BB][NN];
__device__ float    g_iou[BB][NN][NN];      // only upper triangle (i<j) written/read
__device__ unsigned g_ioumaxBits[BB][NN];   // float bits of column max (iou >= 0)
__device__ float    g_kConf[BB][KK];
__device__ float    g_kLoc[BB][KK][4];
__device__ float    g_kMask[BB][KK][DM];
__device__ float    g_fconf[BB][HP * WP];
__device__ double   g_accum[2];             // [0]=var sum, [1]=ae sum
__device__ int      g_vcnt;                 // k_var completion counter

// ---------------- helpers ----------------
__device__ __forceinline__ float blockReduceSum(float v, float* sm) {
    int lane = threadIdx.x & 31, warp = threadIdx.x >> 5;
#pragma unroll
    for (int o = 16; o; o >>= 1) v += __shfl_down_sync(0xffffffffu, v, o);
    if (lane == 0) sm[warp] = v;
    __syncthreads();
    int nw = (blockDim.x + 31) >> 5;
    v = (threadIdx.x < nw) ? sm[threadIdx.x] : 0.f;
    if (warp == 0) {
#pragma unroll
        for (int o = 16; o; o >>= 1) v += __shfl_down_sync(0xffffffffu, v, o);
    }
    return v;  // valid in thread 0
}

// ---------------- kernel 1: softmax + exact top-100 (radix select) + gaussians ----------------
// One block per batch, 1024 threads. Keys = (float bits << 32) | ~idx, so
// descending key order == (value desc, index asc) == lax.top_k tie semantics.
// After selection, the same block renders all 100 32x32 gaussians (iteration k
// -> gaussian k, thread t -> pixel t) with per-warp reduce + smem atomic sums.
__global__ void k_topk(const float* __restrict__ conf, const float* __restrict__ loc) {
    extern __shared__ float vals[];            // PP floats
    __shared__ int hist[256];
    __shared__ int s_bin, s_need;
    __shared__ unsigned long long cand[256];
    __shared__ int s_cnt;
    __shared__ float s_loc4[NN][4];
    __shared__ float s_gsum[NN];
    int b = blockIdx.x, t = threadIdx.x;
    int lane = t & 31;

    const float2* cb = (const float2*)(conf + (size_t)b * PP * 2);
    for (int i = t; i < PP; i += 1024) {
        float2 c = cb[i];
        float m = fmaxf(c.x, c.y);
        float e0 = expf(c.x - m), e1 = expf(c.y - m);
        vals[i] = e1 / (e0 + e1);              // softmax(...)[:,1] in (0,1)
    }
    if (b == 0 && t < 2) g_accum[t] = 0.0;
    if (b == 0 && t == 2) g_vcnt = 0;
    if (t < NN) { g_ioumaxBits[b][t] = 0u; s_gsum[t] = 0.f; }
    __syncthreads();

    // 3 radix passes on the positive-float bit pattern (monotone in value)
    unsigned prefix = 0;
    int need = NN;
    for (int pass = 0; pass < 3; pass++) {
        int shift = 24 - 8 * pass;
        if (t < 256) hist[t] = 0;
        __syncthreads();
        for (int i = t; i < PP; i += 1024) {
            unsigned bv = __float_as_uint(vals[i]);
            bool ok = (pass == 0) || ((bv >> (shift + 8)) == prefix);
            if (ok) atomicAdd(&hist[(bv >> shift) & 0xFF], 1);
        }
        __syncthreads();
        if (t == 0) {
            int cum = 0, bin = 0;
            for (int q = 255; q >= 0; q--) {
                cum += hist[q];
                if (cum >= need) { bin = q; break; }
            }
            s_bin = bin;
            s_need = need - (cum - hist[bin]);  // remaining quota inside this bin
        }
        __syncthreads();
        prefix = (prefix << 8) | (unsigned)s_bin;
        need = s_need;
        __syncthreads();
    }
    unsigned thr = prefix << 8;                 // lower bound of final bin

    // collect candidates (>= thr)
    if (t == 0) s_cnt = 0;
    __syncthreads();
    for (int i = t; i < PP; i += 1024) {
        unsigned bv = __float_as_uint(vals[i]);
        if (bv >= thr) {
            int p = atomicAdd(&s_cnt, 1);
            if (p < 256)
                cand[p] = ((unsigned long long)bv << 32) | (unsigned)(~i);
        }
    }
    __syncthreads();
    if (t < 256 && t >= s_cnt) cand[t] = 0ULL;
    __syncthreads();

    // bitonic sort 256 keys, descending
    for (int k = 2; k <= 256; k <<= 1) {
        for (int j = k >> 1; j > 0; j >>= 1) {
            if (t < 256) {
                int ixj = t ^ j;
                if (ixj > t) {
                    unsigned long long a = cand[t], c = cand[ixj];
                    bool up = ((t & k) == 0);   // descending in "up" segments
                    if (up ? (a < c) : (a > c)) { cand[t] = c; cand[ixj] = a; }
                }
            }
            __syncthreads();
        }
    }

    if (t < NN) {
        unsigned long long key = cand[t];
        g_sConf[b][t] = __uint_as_float((unsigned)(key >> 32));
        g_sIdx[b][t] = (int)(~(unsigned)key);
    }
    const float* lb = loc + (size_t)b * PP * 4;
    if (t < NN * 4) {
        int r = t >> 2, c = t & 3;
        int idx = (int)(~(unsigned)cand[r]);
        float v = lb[(size_t)idx * 4 + c];
        g_sLoc[b][r][c] = v;
        s_loc4[r][c] = v;
    }
    __syncthreads();

    // fused gaussians: iteration k -> gaussian k, thread t -> pixel t (1024 px)
    {
        int y = t >> 5, x = t & 31;
        float fx = (x + 0.5f) / (float)HG, fy = (y + 0.5f) / (float)HG;
#pragma unroll 4
        for (int k = 0; k < NN; k++) {
            float cx = s_loc4[k][0], cy = s_loc4[k][1];
            float wv = s_loc4[k][2] + 1e-4f, hv = s_loc4[k][3] + 1e-4f;
            float dx = (fx - cx) / wv;
            float dy = (fy - cy) / hv;
            float g = expf(-0.5f * (dx * dx + dy * dy));
            g_gauss[b][k][t] = g;
            float s = g;
#pragma unroll
            for (int o = 16; o; o >>= 1) s += __shfl_down_sync(0xffffffffu, s, o);
            if (lane == 0) atomicAdd(&s_gsum[k], s);
        }
    }
    __syncthreads();
    if (t < NN) g_gsum[b][t] = s_gsum[t];
}

// ---------------- kernel 2: tiled pairwise gaussian IoU + fused column max ----------------
// Block = 256 threads = 8 warps, one 8x8 (i,j) tile of pairs. Gi rows live in
// registers (one row per warp), Gj tile in smem. Column max folded via atomicMax
// on float bits (iou >= 0, so uint compare == float compare).
__global__ void k_iou() {
    __shared__ float Gj[TI][HG * HG];   // 32 KB
    int b = blockIdx.y, t = threadIdx.x;
    int w = t >> 5, l = t & 31;

    // map blockIdx.x -> (ti, tj), ti <= tj
    int tp = blockIdx.x, ti = 0;
    while (tp >= NT - ti) { tp -= NT - ti; ti++; }
    int tj = ti + tp;

    // cooperative load of Gj tile (float4), zero-pad rows >= NN
    for (int q = t; q < TI * (HG * HG / 4); q += 256) {
        int jj = q >> 8, c4 = q & 255;
        int j = tj * TI + jj;
        float4 v = make_float4(0.f, 0.f, 0.f, 0.f);
        if (j < NN) v = ((const float4*)g_gauss[b][j])[c4];
        ((float4*)Gj[jj])[c4] = v;
    }
    // Gi row for this warp into registers
    int i = ti * TI + w;
    const float4* grow = (const float4*)g_gauss[b][(i < NN) ? i : 0];
    float4 gi[8];
#pragma unroll
    for (int it = 0; it < 8; it++)
        gi[it] = (i < NN) ? grow[it * 32 + l] : make_float4(0.f, 0.f, 0.f, 0.f);
    __syncthreads();

#pragma unroll
    for (int jj = 0; jj < TI; jj++) {
        int j = tj * TI + jj;
        float s = 0.f;
        const float4* gjr = (const float4*)Gj[jj];
#pragma unroll
        for (int it = 0; it < 8; it++) {
            float4 a = gi[it];
            float4 c = gjr[it * 32 + l];
            s += fminf(a.x, c.x) + fminf(a.y, c.y) + fminf(a.z, c.z) + fminf(a.w, c.w);
        }
#pragma unroll
        for (int o = 16; o; o >>= 1) s += __shfl_down_sync(0xffffffffu, s, o);
        if (l == 0 && i < NN && j < NN && i < j) {
            float u = g_gsum[b][i] + g_gsum[b][j] - s;
            float iouv = s / u;
            g_iou[b][i][j] = iouv;
            atomicMax(&g_ioumaxBits[b][j], __float_as_uint(iouv));
        }
    }
}

// ---------------- kernel 3: keep top-20 (min iou_max, index asc), gathers, AE loss ----------------
__global__ void k_keep(const float* __restrict__ mask) {
    __shared__ float ioumax[NN];
    __shared__ float sconf[NN];
    __shared__ int keep_s[KK];
    __shared__ float rs_s[KK];
    __shared__ float aepart[KK];
    int b = blockIdx.x, t = threadIdx.x;  // 128 threads
    int w = t >> 5, l = t & 31;

    if (t < NN) {
        ioumax[t] = __uint_as_float(g_ioumaxBits[b][t]);
        sconf[t] = g_sConf[b][t];
    }
    __syncthreads();

    // warp 0: 20 rounds of min over (value bits, index) keys
    if (t < 32) {
        for (int r = 0; r < KK; r++) {
            unsigned long long best = ~0ULL;
            for (int j = t; j < NN; j += 32) {
                unsigned long long key =
                    ((unsigned long long)__float_as_uint(ioumax[j]) << 32) | (unsigned)j;
                if (key < best) best = key;
            }
#pragma unroll
            for (int o = 16; o; o >>= 1) {
                unsigned long long x = __shfl_down_sync(0xffffffffu, best, o);
                if (x < best) best = x;
            }
            best = __shfl_sync(0xffffffffu, best, 0);
            int j = (int)(unsigned)best;
            if (t == 0) { keep_s[r] = j; ioumax[j] = 3.4e38f; }
            __syncwarp();
        }
    }
    __syncthreads();

    // gathers
    if (t < KK) g_kConf[b][t] = sconf[keep_s[t]];
    if (t < KK * 4) {
        int k = t >> 2, c = t & 3;
        g_kLoc[b][k][c] = g_sLoc[b][keep_s[k]][c];
    }
    for (int q = t; q < KK * DM; q += 128) {
        int k = q >> 5, d = q & (DM - 1);
        int oi = g_sIdx[b][keep_s[k]];
        g_kMask[b][k][d] = mask[((size_t)b * PP + oi) * DM + d];
    }
    __syncthreads();

    // rs[k] = sum_{j>i} iou[i,j]*conf[j], parallel warp-per-kept-row
    for (int k = w; k < KK; k += 4) {
        int i = keep_s[k];
        float s = 0.f;
        for (int j = i + 1 + l; j < NN; j += 32) s += g_iou[b][i][j] * sconf[j];
#pragma unroll
        for (int o = 16; o; o >>= 1) s += __shfl_down_sync(0xffffffffu, s, o);
        if (l == 0) rs_s[k] = s;
    }
    __syncthreads();

    if (t < KK) {
        int i = keep_s[t];
        float al = 0.f;
#pragma unroll
        for (int c = 0; c < 4; c++) {
            float v = g_kLoc[b][t][c];
            al += v * v;
        }
        al *= 0.25f;
        aepart[t] = al * sconf[i] * rs_s[t];
    }
    __syncthreads();
    if (t == 0) {
        double s = 0.0;
        for (int k = 0; k < KK; k++) s += (double)aepart[k];
        atomicAdd(&g_accum[1], s);
    }
}

// ---------------- kernel 4: assembled*gauss*conf -> final_conf on 138x138 ----------------
__global__ void k_fconf(const float* __restrict__ proto) {
    __shared__ float sm_mask[KK][DM];
    __shared__ float sm_loc[KK][4];
    __shared__ float sm_conf[KK];
    int b = blockIdx.y, t = threadIdx.x;  // 128 threads

    for (int q = t; q < KK * DM; q += 128) sm_mask[q / DM][q % DM] = g_kMask[b][q / DM][q % DM];
    if (t < KK * 4) sm_loc[t >> 2][t & 3] = g_kLoc[b][t >> 2][t & 3];
    if (t < KK) sm_conf[t] = g_kConf[b][t];
    __syncthreads();

    int pix = blockIdx.x * 128 + t;
    if (pix >= HP * WP) return;
    int y = pix / WP, x = pix - y * WP;

    const float4* pp = (const float4*)(proto + ((size_t)b * HP * WP + pix) * DM);
    float pr[DM];
#pragma unroll
    for (int q = 0; q < DM / 4; q++) {
        float4 v = pp[q];
        pr[4 * q] = v.x; pr[4 * q + 1] = v.y; pr[4 * q + 2] = v.z; pr[4 * q + 3] = v.w;
    }
    float px_ = (x + 0.5f) / (float)WP, py_ = (y + 0.5f) / (float)HP;
    float s1 = 0.f, s2 = 0.f;
#pragma unroll
    for (int k = 0; k < KK; k++) {
        const float4* mk = (const float4*)sm_mask[k];
        float dot = 0.f;
#pragma unroll
        for (int q = 0; q < DM / 4; q++) {
            float4 mv = mk[q];
            dot = fmaf(pr[4 * q], mv.x, dot);
            dot = fmaf(pr[4 * q + 1], mv.y, dot);
            dot = fmaf(pr[4 * q + 2], mv.z, dot);
            dot = fmaf(pr[4 * q + 3], mv.w, dot);
        }
        float a = 1.f / (1.f + expf(-dot));  // sigmoid
        float dx = (px_ - sm_loc[k][0]) / (sm_loc[k][2] + 1e-4f);
        float dy = (py_ - sm_loc[k][1]) / (sm_loc[k][3] + 1e-4f);
        float ug = expf(-0.5f * (dx * dx + dy * dy));
        float mc = a * ug * sm_conf[k];
        s1 += mc;
        s2 = fmaf(mc, mc, s2);
    }
    float fc = 1.f - s2 / (s1 + 1e-6f);
    if (isnan(fc)) fc = 0.f;
    g_fconf[b][pix] = fc;
}

// ---------------- kernel 5: fused bilinear resize + weighted variance + finalize ----------------
__global__ void k_var(const float* __restrict__ orig, float* __restrict__ out) {
    __shared__ float sm[32];
    int pix = blockIdx.x * 256 + threadIdx.x;
    float local = 0.f;
    if (pix < HH * WW) {
        int h = pix / WW, w = pix - h * WW;
        const float scale = (float)HP / (float)HH;
        float sx = (w + 0.5f) * scale - 0.5f;
        float sy = (h + 0.5f) * scale - 0.5f;
        float fx0 = floorf(sx), fy0 = floorf(sy);
        float ax = sx - fx0, ay = sy - fy0;
        int x0 = min(max((int)fx0, 0), WP - 1);
        int x1 = min(max((int)fx0 + 1, 0), WP - 1);
        int y0 = min(max((int)fy0, 0), HP - 1);
        int y1 = min(max((int)fy0 + 1, 0), HP - 1);
        float w00 = (1.f - ax) * (1.f - ay), w01 = ax * (1.f - ay);
        float w10 = (1.f - ax) * ay, w11 = ax * ay;

        float r0 = g_fconf[0][y0 * WP + x0] * w00 + g_fconf[0][y0 * WP + x1] * w01 +
                   g_fconf[0][y1 * WP + x0] * w10 + g_fconf[0][y1 * WP + x1] * w11;
        float r1 = g_fconf[1][y0 * WP + x0] * w00 + g_fconf[1][y0 * WP + x1] * w01 +
                   g_fconf[1][y1 * WP + x0] * w10 + g_fconf[1][y1 * WP + x1] * w11;
        float total = r0 + r1;
#pragma unroll
        for (int c = 0; c < 3; c++) {
            float o0 = orig[((size_t)(0 * 3 + c) * HH + h) * WW + w];
            float o1 = orig[((size_t)(1 * 3 + c) * HH + h) * WW + w];
            float wm = (o0 * r0 + o1 * r1) / total;
            float d0 = o0 - wm, d1 = o1 - wm;
            local += (d0 * d0 * r0 + d1 * d1 * r1) / (total + 1e-6f);
        }
    }
    float s = blockReduceSum(local, sm);
    if (threadIdx.x == 0) {
        atomicAdd(&g_accum[0], (double)s);
        __threadfence();
        int ticket = atomicAdd(&g_vcnt, 1);
        if (ticket == VAR_BLOCKS - 1) {           // last block finalizes
            double v = atomicAdd(&g_accum[0], 0.0);
            double a = atomicAdd(&g_accum[1], 0.0);
            out[0] = (float)(v / (double)HP * (double)BB);
            out[1] = (float)(a / (double)(BB * NN * NN));
        }
    }
}

// ---------------- launch ----------------
extern "C" void kernel_launch(void* const* d_in, const int* in_sizes, int n_in,
                              void* d_out, int out_size) {
    const float *orig = nullptr, *loc = nullptr, *conf = nullptr, *mask = nullptr, *proto = nullptr;
    for (int i = 0; i < n_in; i++) {
        switch (in_sizes[i]) {
            case BB * 3 * HH * WW:   orig  = (const float*)d_in[i]; break;
            case BB * PP * 4:        loc   = (const float*)d_in[i]; break;
            case BB * PP * 2:        conf  = (const float*)d_in[i]; break;
            case BB * PP * DM:       mask  = (const float*)d_in[i]; break;
            case BB * HP * WP * DM:  proto = (const float*)d_in[i]; break;
            default: break;
        }
    }
    if (!orig || !loc || !conf || !mask || !proto) return;

    cudaFuncSetAttribute(k_topk, cudaFuncAttributeMaxDynamicSharedMemorySize, PP * sizeof(float));

    k_topk<<<BB, 1024, PP * sizeof(float)>>>(conf, loc);
    k_iou<<<dim3(NTP, BB), 256>>>();
    k_keep<<<BB, 128>>>(mask);
    k_fconf<<<dim3((HP * WP + 127) / 128, BB), 128>>>(proto);
    k_var<<<VAR_BLOCKS, 256>>>(orig, (float*)d_out);
}

// round 7
// speedup vs baseline: 1.8755x; 1.3757x over previous
#include <cuda_runtime.h>
#include <math.h>

#define BB 2
#define PP 19248
#define NN 100
#define KK 20
#define HG 32
#define HP 138
#define WP 138
#define HH 550
#define WW 550
#define DM 32
#define TI 8
#define NT 13             // ceil(NN/TI)
#define NTP (NT*(NT+1)/2) // 91 tile pairs (ti<=tj)
#define NPIX (HH * WW)    // 302500
#define NPIX4 (NPIX / 4)  // 75625
#define VAR_BLOCKS ((NPIX4 + 255) / 256)   // 296

// ---------------- scratch (device globals; no allocation allowed) ----------------
__device__ int      g_sIdx[BB][NN];
__device__ float    g_sConf[BB][NN];
__device__ float    g_sLoc[BB][NN][4];
__device__ float    g_ex[BB][NN][HG];       // exp(-.5*dx^2) row factors
__device__ float    g_ey[BB][NN][HG];       // exp(-.5*dy^2) col factors
__device__ float    g_gsum[BB][NN];
__device__ float    g_iou[BB][NN][NN];      // only upper triangle (i<j) written/read
__device__ unsigned g_ioumaxBits[BB][NN];   // float bits of column max (iou >= 0)
__device__ float    g_kConf[BB][KK];
__device__ float    g_kLoc[BB][KK][4];
__device__ float    g_kMask[BB][KK][DM];
__device__ float    g_fconf[BB][HP * WP];
__device__ double   g_accum[2];             // [0]=var sum, [1]=ae sum
__device__ int      g_vcnt;                 // k_var completion counter
__device__ int      g_icnt;                 // k_iou completion counter

// ---------------- helpers ----------------
__device__ __forceinline__ float blockReduceSum(float v, float* sm) {
    int lane = threadIdx.x & 31, warp = threadIdx.x >> 5;
#pragma unroll
    for (int o = 16; o; o >>= 1) v += __shfl_down_sync(0xffffffffu, v, o);
    if (lane == 0) sm[warp] = v;
    __syncthreads();
    int nw = (blockDim.x + 31) >> 5;
    v = (threadIdx.x < nw) ? sm[threadIdx.x] : 0.f;
    if (warp == 0) {
#pragma unroll
        for (int o = 16; o; o >>= 1) v += __shfl_down_sync(0xffffffffu, v, o);
    }
    return v;  // valid in thread 0
}

// ---------------- kernel 1: softmax + exact top-100 (radix select) + separable gaussian factors ----------------
// One block per batch, 1024 threads. Keys = (float bits << 32) | ~idx, so
// descending key order == (value desc, index asc) == lax.top_k tie semantics.
__global__ void k_topk(const float* __restrict__ conf, const float* __restrict__ loc) {
    extern __shared__ float vals[];            // PP floats
    __shared__ int hist[256];
    __shared__ int s_bin, s_need;
    __shared__ unsigned long long cand[256];
    __shared__ int s_cnt;
    __shared__ float s_loc4[NN][4];
    __shared__ float s_sx[NN], s_sy[NN];
    int b = blockIdx.x, t = threadIdx.x;
    int lane = t & 31;

    const float2* cb = (const float2*)(conf + (size_t)b * PP * 2);
    for (int i = t; i < PP; i += 1024) {
        float2 c = cb[i];
        float m = fmaxf(c.x, c.y);
        float e0 = expf(c.x - m), e1 = expf(c.y - m);
        vals[i] = e1 / (e0 + e1);              // softmax(...)[:,1] in (0,1)
    }
    if (b == 0 && t < 2) g_accum[t] = 0.0;
    if (b == 0 && t == 2) g_vcnt = 0;
    if (b == 0 && t == 3) g_icnt = 0;
    if (t < NN) g_ioumaxBits[b][t] = 0u;       // reset every replay
    __syncthreads();

    // 3 radix passes on the positive-float bit pattern (monotone in value)
    unsigned prefix = 0;
    int need = NN;
    for (int pass = 0; pass < 3; pass++) {
        int shift = 24 - 8 * pass;
        if (t < 256) hist[t] = 0;
        __syncthreads();
        for (int i = t; i < PP; i += 1024) {
            unsigned bv = __float_as_uint(vals[i]);
            bool ok = (pass == 0) || ((bv >> (shift + 8)) == prefix);
            if (ok) atomicAdd(&hist[(bv >> shift) & 0xFF], 1);
        }
        __syncthreads();
        if (t == 0) {
            int cum = 0, bin = 0;
            for (int q = 255; q >= 0; q--) {
                cum += hist[q];
                if (cum >= need) { bin = q; break; }
            }
            s_bin = bin;
            s_need = need - (cum - hist[bin]);  // remaining quota inside this bin
        }
        __syncthreads();
        prefix = (prefix << 8) | (unsigned)s_bin;
        need = s_need;
        __syncthreads();
    }
    unsigned thr = prefix << 8;                 // lower bound of final bin

    // collect candidates (>= thr)
    if (t == 0) s_cnt = 0;
    __syncthreads();
    for (int i = t; i < PP; i += 1024) {
        unsigned bv = __float_as_uint(vals[i]);
        if (bv >= thr) {
            int p = atomicAdd(&s_cnt, 1);
            if (p < 256)
                cand[p] = ((unsigned long long)bv << 32) | (unsigned)(~i);
        }
    }
    __syncthreads();
    if (t < 256 && t >= s_cnt) cand[t] = 0ULL;
    __syncthreads();

    // bitonic sort 256 keys, descending
    for (int k = 2; k <= 256; k <<= 1) {
        for (int j = k >> 1; j > 0; j >>= 1) {
            if (t < 256) {
                int ixj = t ^ j;
                if (ixj > t) {
                    unsigned long long a = cand[t], c = cand[ixj];
                    bool up = ((t & k) == 0);   // descending in "up" segments
                    if (up ? (a < c) : (a > c)) { cand[t] = c; cand[ixj] = a; }
                }
            }
            __syncthreads();
        }
    }

    if (t < NN) {
        unsigned long long key = cand[t];
        g_sConf[b][t] = __uint_as_float((unsigned)(key >> 32));
        g_sIdx[b][t] = (int)(~(unsigned)key);
    }
    const float* lb = loc + (size_t)b * PP * 4;
    if (t < NN * 4) {
        int r = t >> 2, c = t & 3;
        int idx = (int)(~(unsigned)cand[r]);
        float v = lb[(size_t)idx * 4 + c];
        g_sLoc[b][r][c] = v;
        s_loc4[r][c] = v;
    }
    __syncthreads();

    // separable gaussian factors: warp handles one gaussian k per iteration
    for (int base = 0; base < NN * HG; base += 1024) {
        int item = base + t, k = item >> 5, l2 = item & 31;
        float v = 0.f;
        if (k < NN) {
            float fx = (l2 + 0.5f) / (float)HG;
            float dx = (fx - s_loc4[k][0]) / (s_loc4[k][2] + 1e-4f);
            v = expf(-0.5f * dx * dx);
            g_ex[b][k][l2] = v;
        }
        float s = v;
#pragma unroll
        for (int o = 16; o; o >>= 1) s += __shfl_down_sync(0xffffffffu, s, o);
        if (lane == 0 && k < NN) s_sx[k] = s;
    }
    for (int base = 0; base < NN * HG; base += 1024) {
        int item = base + t, k = item >> 5, l2 = item & 31;
        float v = 0.f;
        if (k < NN) {
            float fy = (l2 + 0.5f) / (float)HG;
            float dy = (fy - s_loc4[k][1]) / (s_loc4[k][3] + 1e-4f);
            v = expf(-0.5f * dy * dy);
            g_ey[b][k][l2] = v;
        }
        float s = v;
#pragma unroll
        for (int o = 16; o; o >>= 1) s += __shfl_down_sync(0xffffffffu, s, o);
        if (lane == 0 && k < NN) s_sy[k] = s;
    }
    __syncthreads();
    if (t < NN) g_gsum[b][t] = s_sx[t] * s_sy[t];
}

// ---------------- kernel 2: pairwise gaussian IoU from separable factors + fused keep/AE tail ----------------
// Block = 256 threads = 8 warps, one 8x8 (i,j) tile of pairs reconstructed from
// ex/ey outer products (no materialized gaussians). Column max folded via
// atomicMax on float bits. The last-finishing block (threadfence-reduction
// pattern) runs the keep/top-20 selection, gathers, and AE loss for both batches.
__global__ void k_iou(const float* __restrict__ mask) {
    __shared__ float s_exi[TI][HG], s_eyi[TI][HG], s_exj[TI][HG], s_eyj[TI][HG];
    __shared__ float s_gi[TI], s_gj[TI];
    __shared__ bool amLast;
    int b = blockIdx.y, t = threadIdx.x;
    int w = t >> 5, l = t & 31;

    // map blockIdx.x -> (ti, tj), ti <= tj
    int tp = blockIdx.x, ti = 0;
    while (tp >= NT - ti) { tp -= NT - ti; ti++; }
    int tj = ti + tp;

    for (int q = t; q < TI * HG; q += 256) {
        int r = q >> 5, c = q & 31;
        int gi = ti * TI + r, gj = tj * TI + r;
        s_exi[r][c] = (gi < NN) ? g_ex[b][gi][c] : 0.f;
        s_eyi[r][c] = (gi < NN) ? g_ey[b][gi][c] : 0.f;
        s_exj[r][c] = (gj < NN) ? g_ex[b][gj][c] : 0.f;
        s_eyj[r][c] = (gj < NN) ? g_ey[b][gj][c] : 0.f;
    }
    if (t < TI) {
        int gi = ti * TI + t, gj = tj * TI + t;
        s_gi[t] = (gi < NN) ? g_gsum[b][gi] : 0.f;
        s_gj[t] = (gj < NN) ? g_gsum[b][gj] : 0.f;
    }
    __syncthreads();

    int i = ti * TI + w;
    float exi_l = s_exi[w][l];
    float exj_r[TI];
    float acc[TI];
#pragma unroll
    for (int jj = 0; jj < TI; jj++) { exj_r[jj] = s_exj[jj][l]; acc[jj] = 0.f; }

    for (int y = 0; y < HG; y++) {
        float a = s_eyi[w][y] * exi_l;
#pragma unroll
        for (int jj = 0; jj < TI; jj++) {
            float bm = s_eyj[jj][y] * exj_r[jj];
            acc[jj] += fminf(a, bm);
        }
    }
#pragma unroll
    for (int jj = 0; jj < TI; jj++) {
        float s = acc[jj];
#pragma unroll
        for (int o = 16; o; o >>= 1) s += __shfl_down_sync(0xffffffffu, s, o);
        int j = tj * TI + jj;
        if (l == 0 && i < NN && j < NN && i < j) {
            float u = s_gi[w] + s_gj[jj] - s;
            float iouv = s / u;
            g_iou[b][i][j] = iouv;
            atomicMax(&g_ioumaxBits[b][j], __float_as_uint(iouv));
        }
    }

    // ---- completion counter: last block runs keep + AE for both batches ----
    __threadfence();
    if (t == 0) {
        int ticket = atomicAdd(&g_icnt, 1);
        amLast = (ticket == NTP * BB - 1);
    }
    __syncthreads();
    if (!amLast) return;

    __shared__ float ioumax[NN];
    __shared__ float sconf[NN];
    __shared__ int keep_s[KK];
    __shared__ float rs_s[KK];
    __shared__ float aepart[KK];

    for (int bb = 0; bb < BB; bb++) {
        if (t < NN) {
            ioumax[t] = __uint_as_float(g_ioumaxBits[bb][t]);
            sconf[t] = g_sConf[bb][t];
        }
        __syncthreads();

        // warp 0: 20 rounds of min over (value bits, index) keys
        if (t < 32) {
            for (int r = 0; r < KK; r++) {
                unsigned long long best = ~0ULL;
                for (int j = t; j < NN; j += 32) {
                    unsigned long long key =
                        ((unsigned long long)__float_as_uint(ioumax[j]) << 32) | (unsigned)j;
                    if (key < best) best = key;
                }
#pragma unroll
                for (int o = 16; o; o >>= 1) {
                    unsigned long long x = __shfl_down_sync(0xffffffffu, best, o);
                    if (x < best) best = x;
                }
                best = __shfl_sync(0xffffffffu, best, 0);
                int j = (int)(unsigned)best;
                if (t == 0) { keep_s[r] = j; ioumax[j] = 3.4e38f; }
                __syncwarp();
            }
        }
        __syncthreads();

        if (t < KK) g_kConf[bb][t] = sconf[keep_s[t]];
        if (t < KK * 4) {
            int k = t >> 2, c = t & 3;
            g_kLoc[bb][k][c] = g_sLoc[bb][keep_s[k]][c];
        }
        for (int q = t; q < KK * DM; q += 256) {
            int k = q >> 5, d = q & (DM - 1);
            int oi = g_sIdx[bb][keep_s[k]];
            g_kMask[bb][k][d] = mask[((size_t)bb * PP + oi) * DM + d];
        }
        __syncthreads();

        // rs[k] = sum_{j>i} iou[i,j]*conf[j], warp-per-kept-row
        for (int k = w; k < KK; k += 8) {
            int i2 = keep_s[k];
            float s = 0.f;
            for (int j = i2 + 1 + l; j < NN; j += 32) s += g_iou[bb][i2][j] * sconf[j];
#pragma unroll
            for (int o = 16; o; o >>= 1) s += __shfl_down_sync(0xffffffffu, s, o);
            if (l == 0) rs_s[k] = s;
        }
        __syncthreads();

        if (t < KK) {
            int i2 = keep_s[t];
            float al = 0.f;
#pragma unroll
            for (int c = 0; c < 4; c++) {
                float v = g_kLoc[bb][t][c];
                al += v * v;
            }
            al *= 0.25f;
            aepart[t] = al * sconf[i2] * rs_s[t];
        }
        __syncthreads();
        if (t == 0) {
            double s = 0.0;
            for (int k = 0; k < KK; k++) s += (double)aepart[k];
            atomicAdd(&g_accum[1], s);
        }
        __syncthreads();
    }
}

// ---------------- kernel 3: assembled*gauss*conf -> final_conf on 138x138 ----------------
__global__ void k_fconf(const float* __restrict__ proto) {
    __shared__ float sm_mask[KK][DM];
    __shared__ float s_cx[KK], s_cy[KK], s_iw[KK], s_ih[KK], s_cf[KK];
    int b = blockIdx.y, t = threadIdx.x;  // 128 threads

    for (int q = t; q < KK * DM; q += 128) sm_mask[q / DM][q % DM] = g_kMask[b][q / DM][q % DM];
    if (t < KK) {
        s_cx[t] = g_kLoc[b][t][0];
        s_cy[t] = g_kLoc[b][t][1];
        s_iw[t] = 1.f / (g_kLoc[b][t][2] + 1e-4f);
        s_ih[t] = 1.f / (g_kLoc[b][t][3] + 1e-4f);
        s_cf[t] = g_kConf[b][t];
    }
    __syncthreads();

    int pix = blockIdx.x * 128 + t;
    if (pix >= HP * WP) return;
    int y = pix / WP, x = pix - y * WP;

    const float4* pp = (const float4*)(proto + ((size_t)b * HP * WP + pix) * DM);
    float pr[DM];
#pragma unroll
    for (int q = 0; q < DM / 4; q++) {
        float4 v = pp[q];
        pr[4 * q] = v.x; pr[4 * q + 1] = v.y; pr[4 * q + 2] = v.z; pr[4 * q + 3] = v.w;
    }
    float px_ = (x + 0.5f) / (float)WP, py_ = (y + 0.5f) / (float)HP;
    float s1 = 0.f, s2 = 0.f;
#pragma unroll 2
    for (int k = 0; k < KK; k++) {
        const float4* mk = (const float4*)sm_mask[k];
        float d0 = 0.f, d1 = 0.f, d2 = 0.f, d3 = 0.f;
#pragma unroll
        for (int q = 0; q < DM / 4; q++) {
            float4 mv = mk[q];
            d0 = fmaf(pr[4 * q], mv.x, d0);
            d1 = fmaf(pr[4 * q + 1], mv.y, d1);
            d2 = fmaf(pr[4 * q + 2], mv.z, d2);
            d3 = fmaf(pr[4 * q + 3], mv.w, d3);
        }
        float dot = (d0 + d1) + (d2 + d3);
        float a = __fdividef(1.f, 1.f + __expf(-dot));   // sigmoid
        float dx = (px_ - s_cx[k]) * s_iw[k];
        float dy = (py_ - s_cy[k]) * s_ih[k];
        float ug = __expf(-0.5f * fmaf(dx, dx, dy * dy));
        float mc = a * ug * s_cf[k];
        s1 += mc;
        s2 = fmaf(mc, mc, s2);
    }
    float fc = 1.f - __fdividef(s2, s1 + 1e-6f);
    if (isnan(fc)) fc = 0.f;
    g_fconf[b][pix] = fc;
}

// ---------------- kernel 4: fused bilinear resize + weighted variance + finalize ----------------
__global__ void k_var(const float* __restrict__ orig, float* __restrict__ out) {
    __shared__ float sm[32];
    int p4 = blockIdx.x * 256 + threadIdx.x;
    float local = 0.f;
    if (p4 < NPIX4) {
        // vectorized channel loads: 4 consecutive pixels per thread
        float4 ov[2][3];
#pragma unroll
        for (int b2 = 0; b2 < 2; b2++)
#pragma unroll
            for (int c = 0; c < 3; c++)
                ov[b2][c] = ((const float4*)orig)[(size_t)(b2 * 3 + c) * NPIX4 + p4];

        int base = p4 * 4;
#pragma unroll
        for (int e = 0; e < 4; e++) {
            int pix = base + e;
            int h = pix / WW, w = pix - h * WW;
            const float scale = (float)HP / (float)HH;
            float sx = (w + 0.5f) * scale - 0.5f;
            float sy = (h + 0.5f) * scale - 0.5f;
            float fx0 = floorf(sx), fy0 = floorf(sy);
            float ax = sx - fx0, ay = sy - fy0;
            int x0 = min(max((int)fx0, 0), WP - 1);
            int x1 = min(max((int)fx0 + 1, 0), WP - 1);
            int y0 = min(max((int)fy0, 0), HP - 1);
            int y1 = min(max((int)fy0 + 1, 0), HP - 1);
            float w00 = (1.f - ax) * (1.f - ay), w01 = ax * (1.f - ay);
            float w10 = (1.f - ax) * ay, w11 = ax * ay;

            float r0 = g_fconf[0][y0 * WP + x0] * w00 + g_fconf[0][y0 * WP + x1] * w01 +
                       g_fconf[0][y1 * WP + x0] * w10 + g_fconf[0][y1 * WP + x1] * w11;
            float r1 = g_fconf[1][y0 * WP + x0] * w00 + g_fconf[1][y0 * WP + x1] * w01 +
                       g_fconf[1][y1 * WP + x0] * w10 + g_fconf[1][y1 * WP + x1] * w11;
            float total = r0 + r1;
            float invT = __fdividef(1.f, total);
            float invTe = __fdividef(1.f, total + 1e-6f);
#pragma unroll
            for (int c = 0; c < 3; c++) {
                float o0 = ((const float*)&ov[0][c])[e];
                float o1 = ((const float*)&ov[1][c])[e];
                float wm = (o0 * r0 + o1 * r1) * invT;
                float dd0 = o0 - wm, dd1 = o1 - wm;
                local += (dd0 * dd0 * r0 + dd1 * dd1 * r1) * invTe;
            }
        }
    }
    float s = blockReduceSum(local, sm);
    if (threadIdx.x == 0) {
        atomicAdd(&g_accum[0], (double)s);
        __threadfence();
        int ticket = atomicAdd(&g_vcnt, 1);
        if (ticket == VAR_BLOCKS - 1) {           // last block finalizes
            double v = atomicAdd(&g_accum[0], 0.0);
            double a = atomicAdd(&g_accum[1], 0.0);
            out[0] = (float)(v / (double)HP * (double)BB);
            out[1] = (float)(a / (double)(BB * NN * NN));
        }
    }
}

// ---------------- launch ----------------
extern "C" void kernel_launch(void* const* d_in, const int* in_sizes, int n_in,
                              void* d_out, int out_size) {
    const float *orig = nullptr, *loc = nullptr, *conf = nullptr, *mask = nullptr, *proto = nullptr;
    for (int i = 0; i < n_in; i++) {
        switch (in_sizes[i]) {
            case BB * 3 * HH * WW:   orig  = (const float*)d_in[i]; break;
            case BB * PP * 4:        loc   = (const float*)d_in[i]; break;
            case BB * PP * 2:        conf  = (const float*)d_in[i]; break;
            case BB * PP * DM:       mask  = (const float*)d_in[i]; break;
            case BB * HP * WP * DM:  proto = (const float*)d_in[i]; break;
            default: break;
        }
    }
    if (!orig || !loc || !conf || !mask || !proto) return;

    cudaFuncSetAttribute(k_topk, cudaFuncAttributeMaxDynamicSharedMemorySize, PP * sizeof(float));

    k_topk<<<BB, 1024, PP * sizeof(float)>>>(conf, loc);
    k_iou<<<dim3(NTP, BB), 256>>>(mask);
    k_fconf<<<dim3((HP * WP + 127) / 128, BB), 128>>>(proto);
    k_var<<<VAR_BLOCKS, 256>>>(orig, (float*)d_out);
}